// round 9
// baseline (speedup 1.0000x reference)
#include <cuda_runtime.h>

#define D 128
#define PMAX 512
#define START_SZ 16384
#define RPW 8            // rows per warp

__device__ float g_vtab[PMAX * D];   // v[p][k] = sum_d W1[d][k] * w2_eff(p)[d]
__device__ float g_ctab[PMAX];       // c[p]    = b1 . w2_eff(p) + b2
__device__ int   g_start[START_SZ];  // first row index of each segment id
__device__ int   g_lastb;            // batch[n-1]

// ---------------------------------------------------------------------------
// Kernel 0: segment boundaries + last segment id (batch is int32)
// ---------------------------------------------------------------------------
__global__ void k_bounds(const int* __restrict__ batch, int n) {
    int i = blockIdx.x * blockDim.x + threadIdx.x;
    if (i >= n) return;
    int b = batch[i];
    if (i == 0 || batch[i - 1] != b) {
        if (b >= 0 && b < START_SZ) g_start[b] = i;
    }
    if (i == n - 1) g_lastb = b;
}

// ---------------------------------------------------------------------------
// Kernel 1: per-position fused weight table
// ---------------------------------------------------------------------------
__global__ void k_table(const float* __restrict__ W1, const float* __restrict__ b1,
                        const float* __restrict__ W2, const float* __restrict__ b2) {
    __shared__ float eff[D];
    int p = blockIdx.x;
    int t = threadIdx.x;
    if (t < D / 2) {
        double theta = pow(10000.0, -2.0 * t / (double)D);
        double ang = (double)p * theta;
        double c = cos(ang), s = sin(ang);
        float w0 = W2[2 * t], w1 = W2[2 * t + 1];
        eff[2 * t]     = (float)(w0 * c + w1 * s);
        eff[2 * t + 1] = (float)(w1 * c - w0 * s);
    }
    __syncthreads();
    float acc = 0.f;
#pragma unroll 8
    for (int d = 0; d < D; d++)
        acc = fmaf(W1[d * D + t], eff[d], acc);
    g_vtab[p * D + t] = acc;
    if (t == 0) {
        float cb = b2[0];
        for (int d = 0; d < D; d++) cb = fmaf(b1[d], eff[d], cb);
        g_ctab[p] = cb;
    }
}

// ---------------------------------------------------------------------------
// Slow-path (pos >= PMAX, never expected): whole warp computes row i on the fly
// ---------------------------------------------------------------------------
__device__ float row_slow(const float4 xv, int pos,
                          const float* __restrict__ W1,
                          const float* __restrict__ b1,
                          const float* __restrict__ W2,
                          const float* __restrict__ b2, int lane) {
    float4 w2v = reinterpret_cast<const float4*>(W2)[lane];
    float eff0, eff1, eff2, eff3;
    {
        int j0 = 2 * lane;
        double th0 = pow(10000.0, -2.0 * j0 / (double)D);
        double a0 = (double)pos * th0;
        double c0 = cos(a0), s0 = sin(a0);
        eff0 = (float)(w2v.x * c0 + w2v.y * s0);
        eff1 = (float)(w2v.y * c0 - w2v.x * s0);
        int j1 = 2 * lane + 1;
        double th1 = pow(10000.0, -2.0 * j1 / (double)D);
        double a1 = (double)pos * th1;
        double c1 = cos(a1), s1 = sin(a1);
        eff2 = (float)(w2v.z * c1 + w2v.w * s1);
        eff3 = (float)(w2v.w * c1 - w2v.z * s1);
    }
    float4 acc = make_float4(0.f, 0.f, 0.f, 0.f);
    const float4* W1r = reinterpret_cast<const float4*>(W1);
    for (int src = 0; src < 32; src++) {
        float e0 = __shfl_sync(0xffffffffu, eff0, src);
        float e1 = __shfl_sync(0xffffffffu, eff1, src);
        float e2 = __shfl_sync(0xffffffffu, eff2, src);
        float e3 = __shfl_sync(0xffffffffu, eff3, src);
        float4 a = W1r[(4 * src + 0) * (D / 4) + lane];
        acc.x = fmaf(a.x, e0, acc.x); acc.y = fmaf(a.y, e0, acc.y);
        acc.z = fmaf(a.z, e0, acc.z); acc.w = fmaf(a.w, e0, acc.w);
        float4 bq = W1r[(4 * src + 1) * (D / 4) + lane];
        acc.x = fmaf(bq.x, e1, acc.x); acc.y = fmaf(bq.y, e1, acc.y);
        acc.z = fmaf(bq.z, e1, acc.z); acc.w = fmaf(bq.w, e1, acc.w);
        float4 cq = W1r[(4 * src + 2) * (D / 4) + lane];
        acc.x = fmaf(cq.x, e2, acc.x); acc.y = fmaf(cq.y, e2, acc.y);
        acc.z = fmaf(cq.z, e2, acc.z); acc.w = fmaf(cq.w, e2, acc.w);
        float4 dq = W1r[(4 * src + 3) * (D / 4) + lane];
        acc.x = fmaf(dq.x, e3, acc.x); acc.y = fmaf(dq.y, e3, acc.y);
        acc.z = fmaf(dq.z, e3, acc.z); acc.w = fmaf(dq.w, e3, acc.w);
    }
    float4 b1v = reinterpret_cast<const float4*>(b1)[lane];
    float partial = xv.x * acc.x + xv.y * acc.y + xv.z * acc.z + xv.w * acc.w
                  + b1v.x * eff0 + b1v.y * eff1 + b1v.z * eff2 + b1v.w * eff3;
#pragma unroll
    for (int o = 16; o; o >>= 1) partial += __shfl_xor_sync(0xffffffffu, partial, o);
    return partial + b2[0];
}

// ---------------------------------------------------------------------------
// Kernel 2: main pass — RPW rows per warp (deep MLP, coalesced stores)
// ---------------------------------------------------------------------------
__global__ __launch_bounds__(256)
void k_main(const float* __restrict__ x,
            const int* __restrict__ batch,
            const float* __restrict__ W1,
            const float* __restrict__ b1,
            const float* __restrict__ W2,
            const float* __restrict__ b2,
            float* __restrict__ out, int n) {
    int warp = (int)((blockIdx.x * blockDim.x + threadIdx.x) >> 5);
    int lane = threadIdx.x & 31;
    int i0 = warp * RPW;
    if (i0 >= n) return;
    int nr = min(RPW, n - i0);

    // lanes 0..nr-1 resolve pos for their row
    int pos_l = 0;
    if (lane < nr) {
        int i = i0 + lane;
        int b = batch[i];
        if (b != g_lastb) {
            int st;
            if (b >= 0 && b < START_SZ) {
                st = g_start[b];
            } else {
                int lo = 0, hi = i;
                while (lo < hi) {
                    int mid = (lo + hi) >> 1;
                    if (batch[mid] < b) lo = mid + 1; else hi = mid;
                }
                st = lo;
            }
            pos_l = i - st;
        }
    }

    // batched independent x loads (MLP = RPW)
    const float4* x4 = reinterpret_cast<const float4*>(x);
    float4 xv[RPW];
#pragma unroll
    for (int r = 0; r < RPW; r++)
        if (r < nr) xv[r] = x4[(size_t)(i0 + r) * (D / 4) + lane];

    // batched vtab loads (L1/L2-resident)
    const float4* v4 = reinterpret_cast<const float4*>(g_vtab);
    int pos[RPW];
    float4 vv[RPW];
    bool any_slow = false;
#pragma unroll
    for (int r = 0; r < RPW; r++) {
        pos[r] = __shfl_sync(0xffffffffu, pos_l, r);
        if (r < nr) {
            int p = pos[r] < PMAX ? pos[r] : 0;
            vv[r] = v4[p * (D / 4) + lane];
            if (pos[r] >= PMAX) any_slow = true;
        }
    }

    // dot + reduce; row r's result kept in lane r
    float res_l = 0.f;
#pragma unroll
    for (int r = 0; r < RPW; r++) {
        if (r >= nr) break;
        float partial;
        if (!any_slow || pos[r] < PMAX) {
            partial = xv[r].x * vv[r].x + xv[r].y * vv[r].y
                    + xv[r].z * vv[r].z + xv[r].w * vv[r].w;
#pragma unroll
            for (int o = 16; o; o >>= 1) partial += __shfl_xor_sync(0xffffffffu, partial, o);
            partial += g_ctab[pos[r]];
        } else {
            partial = row_slow(xv[r], pos[r], W1, b1, W2, b2, lane);
        }
        if (lane == r) res_l = partial;
    }

    if (lane < nr) out[i0 + lane] = res_l;
}

// ---------------------------------------------------------------------------
extern "C" void kernel_launch(void* const* d_in, const int* in_sizes, int n_in,
                              void* d_out, int out_size) {
    const float* x     = (const float*)d_in[0];
    const int*   batch = (const int*)d_in[1];   // int32 (JAX x64 disabled)
    const float* W1    = (const float*)d_in[2];
    const float* b1    = (const float*)d_in[3];
    const float* W2    = (const float*)d_in[4];
    const float* b2    = (const float*)d_in[5];
    float*       out   = (float*)d_out;
    int n = in_sizes[1];

    k_bounds<<<(n + 255) / 256, 256>>>(batch, n);
    k_table<<<PMAX, D>>>(W1, b1, W2, b2);
    int warps = (n + RPW - 1) / RPW;
    int blocks = (warps * 32 + 255) / 256;
    k_main<<<blocks, 256>>>(x, batch, W1, b1, W2, b2, out, n);
}

// round 10
// speedup vs baseline: 1.0404x; 1.0404x over previous
#include <cuda_runtime.h>

#define D 128
#define PMAX 512
#define START_SZ 16384
#define RPW 8            // rows per warp

__device__ float g_vtab[PMAX * D];   // v[p][k] = sum_d W1[d][k] * w2_eff(p)[d]
__device__ float g_ctab[PMAX];       // c[p]    = b1 . w2_eff(p) + b2
__device__ int   g_start[START_SZ];  // first row index of each segment id
__device__ int   g_lastb;            // batch[n-1]

// ---------------------------------------------------------------------------
// Kernel 0: segment boundaries + last segment id (batch is int32)
// ---------------------------------------------------------------------------
__global__ void k_bounds(const int* __restrict__ batch, int n) {
    int i = blockIdx.x * blockDim.x + threadIdx.x;
    if (i >= n) return;
    int b = batch[i];
    if (i == 0 || batch[i - 1] != b) {
        if (b >= 0 && b < START_SZ) g_start[b] = i;
    }
    if (i == n - 1) g_lastb = b;
}

// ---------------------------------------------------------------------------
// Kernel 1: per-position fused weight table
// ---------------------------------------------------------------------------
__global__ void k_table(const float* __restrict__ W1, const float* __restrict__ b1,
                        const float* __restrict__ W2, const float* __restrict__ b2) {
    __shared__ float eff[D];
    int p = blockIdx.x;
    int t = threadIdx.x;
    if (t < D / 2) {
        double theta = pow(10000.0, -2.0 * t / (double)D);
        double ang = (double)p * theta;
        double c = cos(ang), s = sin(ang);
        float w0 = W2[2 * t], w1 = W2[2 * t + 1];
        eff[2 * t]     = (float)(w0 * c + w1 * s);
        eff[2 * t + 1] = (float)(w1 * c - w0 * s);
    }
    __syncthreads();
    float acc = 0.f;
#pragma unroll 8
    for (int d = 0; d < D; d++)
        acc = fmaf(W1[d * D + t], eff[d], acc);
    g_vtab[p * D + t] = acc;
    if (t == 0) {
        float cb = b2[0];
        for (int d = 0; d < D; d++) cb = fmaf(b1[d], eff[d], cb);
        g_ctab[p] = cb;
    }
}

// ---------------------------------------------------------------------------
// Slow-path (pos >= PMAX, never expected): whole warp computes row i on the fly
// ---------------------------------------------------------------------------
__device__ float row_slow(const float4 xv, int pos,
                          const float* __restrict__ W1,
                          const float* __restrict__ b1,
                          const float* __restrict__ W2,
                          const float* __restrict__ b2, int lane) {
    float4 w2v = reinterpret_cast<const float4*>(W2)[lane];
    float eff0, eff1, eff2, eff3;
    {
        int j0 = 2 * lane;
        double th0 = pow(10000.0, -2.0 * j0 / (double)D);
        double a0 = (double)pos * th0;
        double c0 = cos(a0), s0 = sin(a0);
        eff0 = (float)(w2v.x * c0 + w2v.y * s0);
        eff1 = (float)(w2v.y * c0 - w2v.x * s0);
        int j1 = 2 * lane + 1;
        double th1 = pow(10000.0, -2.0 * j1 / (double)D);
        double a1 = (double)pos * th1;
        double c1 = cos(a1), s1 = sin(a1);
        eff2 = (float)(w2v.z * c1 + w2v.w * s1);
        eff3 = (float)(w2v.w * c1 - w2v.z * s1);
    }
    float4 acc = make_float4(0.f, 0.f, 0.f, 0.f);
    const float4* W1r = reinterpret_cast<const float4*>(W1);
    for (int src = 0; src < 32; src++) {
        float e0 = __shfl_sync(0xffffffffu, eff0, src);
        float e1 = __shfl_sync(0xffffffffu, eff1, src);
        float e2 = __shfl_sync(0xffffffffu, eff2, src);
        float e3 = __shfl_sync(0xffffffffu, eff3, src);
        float4 a = W1r[(4 * src + 0) * (D / 4) + lane];
        acc.x = fmaf(a.x, e0, acc.x); acc.y = fmaf(a.y, e0, acc.y);
        acc.z = fmaf(a.z, e0, acc.z); acc.w = fmaf(a.w, e0, acc.w);
        float4 bq = W1r[(4 * src + 1) * (D / 4) + lane];
        acc.x = fmaf(bq.x, e1, acc.x); acc.y = fmaf(bq.y, e1, acc.y);
        acc.z = fmaf(bq.z, e1, acc.z); acc.w = fmaf(bq.w, e1, acc.w);
        float4 cq = W1r[(4 * src + 2) * (D / 4) + lane];
        acc.x = fmaf(cq.x, e2, acc.x); acc.y = fmaf(cq.y, e2, acc.y);
        acc.z = fmaf(cq.z, e2, acc.z); acc.w = fmaf(cq.w, e2, acc.w);
        float4 dq = W1r[(4 * src + 3) * (D / 4) + lane];
        acc.x = fmaf(dq.x, e3, acc.x); acc.y = fmaf(dq.y, e3, acc.y);
        acc.z = fmaf(dq.z, e3, acc.z); acc.w = fmaf(dq.w, e3, acc.w);
    }
    float4 b1v = reinterpret_cast<const float4*>(b1)[lane];
    float partial = xv.x * acc.x + xv.y * acc.y + xv.z * acc.z + xv.w * acc.w
                  + b1v.x * eff0 + b1v.y * eff1 + b1v.z * eff2 + b1v.w * eff3;
#pragma unroll
    for (int o = 16; o; o >>= 1) partial += __shfl_xor_sync(0xffffffffu, partial, o);
    return partial + b2[0];
}

// ---------------------------------------------------------------------------
// Kernel 2: main pass — RPW rows per warp (deep MLP, coalesced stores)
// ---------------------------------------------------------------------------
__global__ __launch_bounds__(256)
void k_main(const float* __restrict__ x,
            const int* __restrict__ batch,
            const float* __restrict__ W1,
            const float* __restrict__ b1,
            const float* __restrict__ W2,
            const float* __restrict__ b2,
            float* __restrict__ out, int n) {
    int warp = (int)((blockIdx.x * blockDim.x + threadIdx.x) >> 5);
    int lane = threadIdx.x & 31;
    int i0 = warp * RPW;
    if (i0 >= n) return;
    int nr = min(RPW, n - i0);

    // lanes 0..nr-1 resolve pos for their row
    int pos_l = 0;
    if (lane < nr) {
        int i = i0 + lane;
        int b = batch[i];
        if (b != g_lastb) {
            int st;
            if (b >= 0 && b < START_SZ) {
                st = g_start[b];
            } else {
                int lo = 0, hi = i;
                while (lo < hi) {
                    int mid = (lo + hi) >> 1;
                    if (batch[mid] < b) lo = mid + 1; else hi = mid;
                }
                st = lo;
            }
            pos_l = i - st;
        }
    }

    // batched independent x loads (MLP = RPW)
    const float4* x4 = reinterpret_cast<const float4*>(x);
    float4 xv[RPW];
#pragma unroll
    for (int r = 0; r < RPW; r++)
        if (r < nr) xv[r] = x4[(size_t)(i0 + r) * (D / 4) + lane];

    // batched vtab loads (L1/L2-resident)
    const float4* v4 = reinterpret_cast<const float4*>(g_vtab);
    int pos[RPW];
    float4 vv[RPW];
    bool any_slow = false;
#pragma unroll
    for (int r = 0; r < RPW; r++) {
        pos[r] = __shfl_sync(0xffffffffu, pos_l, r);
        if (r < nr) {
            int p = pos[r] < PMAX ? pos[r] : 0;
            vv[r] = v4[p * (D / 4) + lane];
            if (pos[r] >= PMAX) any_slow = true;
        }
    }

    // dot + reduce; row r's result kept in lane r
    float res_l = 0.f;
#pragma unroll
    for (int r = 0; r < RPW; r++) {
        if (r >= nr) break;
        float partial;
        if (!any_slow || pos[r] < PMAX) {
            partial = xv[r].x * vv[r].x + xv[r].y * vv[r].y
                    + xv[r].z * vv[r].z + xv[r].w * vv[r].w;
#pragma unroll
            for (int o = 16; o; o >>= 1) partial += __shfl_xor_sync(0xffffffffu, partial, o);
            partial += g_ctab[pos[r]];
        } else {
            partial = row_slow(xv[r], pos[r], W1, b1, W2, b2, lane);
        }
        if (lane == r) res_l = partial;
    }

    if (lane < nr) out[i0 + lane] = res_l;
}

// ---------------------------------------------------------------------------
extern "C" void kernel_launch(void* const* d_in, const int* in_sizes, int n_in,
                              void* d_out, int out_size) {
    const float* x     = (const float*)d_in[0];
    const int*   batch = (const int*)d_in[1];   // int32 (JAX x64 disabled)
    const float* W1    = (const float*)d_in[2];
    const float* b1    = (const float*)d_in[3];
    const float* W2    = (const float*)d_in[4];
    const float* b2    = (const float*)d_in[5];
    float*       out   = (float*)d_out;
    int n = in_sizes[1];

    k_bounds<<<(n + 255) / 256, 256>>>(batch, n);
    k_table<<<PMAX, D>>>(W1, b1, W2, b2);
    int warps = (n + RPW - 1) / RPW;
    int blocks = (warps * 32 + 255) / 256;
    k_main<<<blocks, 256>>>(x, batch, W1, b1, W2, b2, out, n);
}

// round 11
// speedup vs baseline: 1.0491x; 1.0084x over previous
#include <cuda_runtime.h>

#define D 128
#define PMAX 512
#define START_SZ 16384
#define RPW 8            // rows per warp

__device__ float g_vtab[PMAX * D];   // v[p][k] = sum_d W1[d][k] * w2_eff(p)[d]
__device__ float g_ctab[PMAX];       // c[p]    = b1 . w2_eff(p) + b2
__device__ int   g_start[START_SZ];  // first row index of each segment id
__device__ int   g_lastb;            // batch[n-1]

// ---------------------------------------------------------------------------
// Kernel 0: segment boundaries + last segment id (batch is int32)
// ---------------------------------------------------------------------------
__global__ void k_bounds(const int* __restrict__ batch, int n) {
    int i = blockIdx.x * blockDim.x + threadIdx.x;
    if (i >= n) return;
    int b = batch[i];
    if (i == 0 || batch[i - 1] != b) {
        if (b >= 0 && b < START_SZ) g_start[b] = i;
    }
    if (i == n - 1) g_lastb = b;
}

// ---------------------------------------------------------------------------
// Kernel 1: per-position fused weight table
// ---------------------------------------------------------------------------
__global__ void k_table(const float* __restrict__ W1, const float* __restrict__ b1,
                        const float* __restrict__ W2, const float* __restrict__ b2) {
    __shared__ float eff[D];
    int p = blockIdx.x;
    int t = threadIdx.x;
    if (t < D / 2) {
        double theta = pow(10000.0, -2.0 * t / (double)D);
        double ang = (double)p * theta;
        double c = cos(ang), s = sin(ang);
        float w0 = W2[2 * t], w1 = W2[2 * t + 1];
        eff[2 * t]     = (float)(w0 * c + w1 * s);
        eff[2 * t + 1] = (float)(w1 * c - w0 * s);
    }
    __syncthreads();
    float acc = 0.f;
#pragma unroll 8
    for (int d = 0; d < D; d++)
        acc = fmaf(W1[d * D + t], eff[d], acc);
    g_vtab[p * D + t] = acc;
    if (t == 0) {
        float cb = b2[0];
        for (int d = 0; d < D; d++) cb = fmaf(b1[d], eff[d], cb);
        g_ctab[p] = cb;
    }
}

// ---------------------------------------------------------------------------
// Slow-path (pos >= PMAX, never expected): whole warp computes row i on the fly
// ---------------------------------------------------------------------------
__device__ float row_slow(const float4 xv, int pos,
                          const float* __restrict__ W1,
                          const float* __restrict__ b1,
                          const float* __restrict__ W2,
                          const float* __restrict__ b2, int lane) {
    float4 w2v = reinterpret_cast<const float4*>(W2)[lane];
    float eff0, eff1, eff2, eff3;
    {
        int j0 = 2 * lane;
        double th0 = pow(10000.0, -2.0 * j0 / (double)D);
        double a0 = (double)pos * th0;
        double c0 = cos(a0), s0 = sin(a0);
        eff0 = (float)(w2v.x * c0 + w2v.y * s0);
        eff1 = (float)(w2v.y * c0 - w2v.x * s0);
        int j1 = 2 * lane + 1;
        double th1 = pow(10000.0, -2.0 * j1 / (double)D);
        double a1 = (double)pos * th1;
        double c1 = cos(a1), s1 = sin(a1);
        eff2 = (float)(w2v.z * c1 + w2v.w * s1);
        eff3 = (float)(w2v.w * c1 - w2v.z * s1);
    }
    float4 acc = make_float4(0.f, 0.f, 0.f, 0.f);
    const float4* W1r = reinterpret_cast<const float4*>(W1);
    for (int src = 0; src < 32; src++) {
        float e0 = __shfl_sync(0xffffffffu, eff0, src);
        float e1 = __shfl_sync(0xffffffffu, eff1, src);
        float e2 = __shfl_sync(0xffffffffu, eff2, src);
        float e3 = __shfl_sync(0xffffffffu, eff3, src);
        float4 a = W1r[(4 * src + 0) * (D / 4) + lane];
        acc.x = fmaf(a.x, e0, acc.x); acc.y = fmaf(a.y, e0, acc.y);
        acc.z = fmaf(a.z, e0, acc.z); acc.w = fmaf(a.w, e0, acc.w);
        float4 bq = W1r[(4 * src + 1) * (D / 4) + lane];
        acc.x = fmaf(bq.x, e1, acc.x); acc.y = fmaf(bq.y, e1, acc.y);
        acc.z = fmaf(bq.z, e1, acc.z); acc.w = fmaf(bq.w, e1, acc.w);
        float4 cq = W1r[(4 * src + 2) * (D / 4) + lane];
        acc.x = fmaf(cq.x, e2, acc.x); acc.y = fmaf(cq.y, e2, acc.y);
        acc.z = fmaf(cq.z, e2, acc.z); acc.w = fmaf(cq.w, e2, acc.w);
        float4 dq = W1r[(4 * src + 3) * (D / 4) + lane];
        acc.x = fmaf(dq.x, e3, acc.x); acc.y = fmaf(dq.y, e3, acc.y);
        acc.z = fmaf(dq.z, e3, acc.z); acc.w = fmaf(dq.w, e3, acc.w);
    }
    float4 b1v = reinterpret_cast<const float4*>(b1)[lane];
    float partial = xv.x * acc.x + xv.y * acc.y + xv.z * acc.z + xv.w * acc.w
                  + b1v.x * eff0 + b1v.y * eff1 + b1v.z * eff2 + b1v.w * eff3;
#pragma unroll
    for (int o = 16; o; o >>= 1) partial += __shfl_xor_sync(0xffffffffu, partial, o);
    return partial + b2[0];
}

// ---------------------------------------------------------------------------
// Kernel 2: main pass — RPW rows per warp (deep MLP, coalesced stores)
// ---------------------------------------------------------------------------
__global__ __launch_bounds__(256)
void k_main(const float* __restrict__ x,
            const int* __restrict__ batch,
            const float* __restrict__ W1,
            const float* __restrict__ b1,
            const float* __restrict__ W2,
            const float* __restrict__ b2,
            float* __restrict__ out, int n) {
    int warp = (int)((blockIdx.x * blockDim.x + threadIdx.x) >> 5);
    int lane = threadIdx.x & 31;
    int i0 = warp * RPW;
    if (i0 >= n) return;
    int nr = min(RPW, n - i0);

    // lanes 0..nr-1 resolve pos for their row
    int pos_l = 0;
    if (lane < nr) {
        int i = i0 + lane;
        int b = batch[i];
        if (b != g_lastb) {
            int st;
            if (b >= 0 && b < START_SZ) {
                st = g_start[b];
            } else {
                int lo = 0, hi = i;
                while (lo < hi) {
                    int mid = (lo + hi) >> 1;
                    if (batch[mid] < b) lo = mid + 1; else hi = mid;
                }
                st = lo;
            }
            pos_l = i - st;
        }
    }

    // batched independent x loads (MLP = RPW)
    const float4* x4 = reinterpret_cast<const float4*>(x);
    float4 xv[RPW];
#pragma unroll
    for (int r = 0; r < RPW; r++)
        if (r < nr) xv[r] = x4[(size_t)(i0 + r) * (D / 4) + lane];

    // batched vtab loads (L1/L2-resident)
    const float4* v4 = reinterpret_cast<const float4*>(g_vtab);
    int pos[RPW];
    float4 vv[RPW];
    bool any_slow = false;
#pragma unroll
    for (int r = 0; r < RPW; r++) {
        pos[r] = __shfl_sync(0xffffffffu, pos_l, r);
        if (r < nr) {
            int p = pos[r] < PMAX ? pos[r] : 0;
            vv[r] = v4[p * (D / 4) + lane];
            if (pos[r] >= PMAX) any_slow = true;
        }
    }

    // dot + reduce; row r's result kept in lane r
    float res_l = 0.f;
#pragma unroll
    for (int r = 0; r < RPW; r++) {
        if (r >= nr) break;
        float partial;
        if (!any_slow || pos[r] < PMAX) {
            partial = xv[r].x * vv[r].x + xv[r].y * vv[r].y
                    + xv[r].z * vv[r].z + xv[r].w * vv[r].w;
#pragma unroll
            for (int o = 16; o; o >>= 1) partial += __shfl_xor_sync(0xffffffffu, partial, o);
            partial += g_ctab[pos[r]];
        } else {
            partial = row_slow(xv[r], pos[r], W1, b1, W2, b2, lane);
        }
        if (lane == r) res_l = partial;
    }

    if (lane < nr) out[i0 + lane] = res_l;
}

// ---------------------------------------------------------------------------
extern "C" void kernel_launch(void* const* d_in, const int* in_sizes, int n_in,
                              void* d_out, int out_size) {
    const float* x     = (const float*)d_in[0];
    const int*   batch = (const int*)d_in[1];   // int32 (JAX x64 disabled)
    const float* W1    = (const float*)d_in[2];
    const float* b1    = (const float*)d_in[3];
    const float* W2    = (const float*)d_in[4];
    const float* b2    = (const float*)d_in[5];
    float*       out   = (float*)d_out;
    int n = in_sizes[1];

    k_bounds<<<(n + 255) / 256, 256>>>(batch, n);
    k_table<<<PMAX, D>>>(W1, b1, W2, b2);
    int warps = (n + RPW - 1) / RPW;
    int blocks = (warps * 32 + 255) / 256;
    k_main<<<blocks, 256>>>(x, batch, W1, b1, W2, b2, out, n);
}

// round 12
// speedup vs baseline: 1.8079x; 1.7233x over previous
#include <cuda_runtime.h>

#define D 128
#define PMAX 512
#define START_SZ 16384
#define RPW 4            // rows per warp (registers stay ~50, no spill)

__device__ float g_vtab[PMAX * D];   // v[p][k] = sum_d W1[d][k] * w2_eff(p)[d]
__device__ float g_ctab[PMAX];       // c[p]    = b1 . w2_eff(p) + b2
__device__ int   g_start[START_SZ];  // first row index of each segment id
__device__ int   g_lastb;            // batch[n-1]

// ---------------------------------------------------------------------------
// Kernel 0: segment boundaries + last segment id (batch is int32)
// ---------------------------------------------------------------------------
__global__ void k_bounds(const int* __restrict__ batch, int n) {
    int i = blockIdx.x * blockDim.x + threadIdx.x;
    if (i >= n) return;
    int b = batch[i];
    if (i == 0 || batch[i - 1] != b) {
        if (b >= 0 && b < START_SZ) g_start[b] = i;
    }
    if (i == n - 1) g_lastb = b;
}

// ---------------------------------------------------------------------------
// Kernel 1: per-position fused weight table
// ---------------------------------------------------------------------------
__global__ void k_table(const float* __restrict__ W1, const float* __restrict__ b1,
                        const float* __restrict__ W2, const float* __restrict__ b2) {
    __shared__ float eff[D];
    int p = blockIdx.x;
    int t = threadIdx.x;
    if (t < D / 2) {
        double theta = pow(10000.0, -2.0 * t / (double)D);
        double ang = (double)p * theta;
        double c = cos(ang), s = sin(ang);
        float w0 = W2[2 * t], w1 = W2[2 * t + 1];
        eff[2 * t]     = (float)(w0 * c + w1 * s);
        eff[2 * t + 1] = (float)(w1 * c - w0 * s);
    }
    __syncthreads();
    float acc = 0.f;
#pragma unroll 8
    for (int d = 0; d < D; d++)
        acc = fmaf(W1[d * D + t], eff[d], acc);
    g_vtab[p * D + t] = acc;
    if (t == 0) {
        float cb = b2[0];
        for (int d = 0; d < D; d++) cb = fmaf(b1[d], eff[d], cb);
        g_ctab[p] = cb;
    }
}

// ---------------------------------------------------------------------------
// Slow path (pos >= PMAX, never expected on this input)
// ---------------------------------------------------------------------------
__device__ float row_slow(const float4 xv, int pos,
                          const float* __restrict__ W1,
                          const float* __restrict__ b1,
                          const float* __restrict__ W2,
                          const float* __restrict__ b2, int lane) {
    float4 w2v = reinterpret_cast<const float4*>(W2)[lane];
    float eff0, eff1, eff2, eff3;
    {
        int j0 = 2 * lane;
        double th0 = pow(10000.0, -2.0 * j0 / (double)D);
        double a0 = (double)pos * th0;
        double c0 = cos(a0), s0 = sin(a0);
        eff0 = (float)(w2v.x * c0 + w2v.y * s0);
        eff1 = (float)(w2v.y * c0 - w2v.x * s0);
        int j1 = 2 * lane + 1;
        double th1 = pow(10000.0, -2.0 * j1 / (double)D);
        double a1 = (double)pos * th1;
        double c1 = cos(a1), s1 = sin(a1);
        eff2 = (float)(w2v.z * c1 + w2v.w * s1);
        eff3 = (float)(w2v.w * c1 - w2v.z * s1);
    }
    float4 acc = make_float4(0.f, 0.f, 0.f, 0.f);
    const float4* W1r = reinterpret_cast<const float4*>(W1);
    for (int src = 0; src < 32; src++) {
        float e0 = __shfl_sync(0xffffffffu, eff0, src);
        float e1 = __shfl_sync(0xffffffffu, eff1, src);
        float e2 = __shfl_sync(0xffffffffu, eff2, src);
        float e3 = __shfl_sync(0xffffffffu, eff3, src);
        float4 a = W1r[(4 * src + 0) * (D / 4) + lane];
        acc.x = fmaf(a.x, e0, acc.x); acc.y = fmaf(a.y, e0, acc.y);
        acc.z = fmaf(a.z, e0, acc.z); acc.w = fmaf(a.w, e0, acc.w);
        float4 bq = W1r[(4 * src + 1) * (D / 4) + lane];
        acc.x = fmaf(bq.x, e1, acc.x); acc.y = fmaf(bq.y, e1, acc.y);
        acc.z = fmaf(bq.z, e1, acc.z); acc.w = fmaf(bq.w, e1, acc.w);
        float4 cq = W1r[(4 * src + 2) * (D / 4) + lane];
        acc.x = fmaf(cq.x, e2, acc.x); acc.y = fmaf(cq.y, e2, acc.y);
        acc.z = fmaf(cq.z, e2, acc.z); acc.w = fmaf(cq.w, e2, acc.w);
        float4 dq = W1r[(4 * src + 3) * (D / 4) + lane];
        acc.x = fmaf(dq.x, e3, acc.x); acc.y = fmaf(dq.y, e3, acc.y);
        acc.z = fmaf(dq.z, e3, acc.z); acc.w = fmaf(dq.w, e3, acc.w);
    }
    float4 b1v = reinterpret_cast<const float4*>(b1)[lane];
    float partial = xv.x * acc.x + xv.y * acc.y + xv.z * acc.z + xv.w * acc.w
                  + b1v.x * eff0 + b1v.y * eff1 + b1v.z * eff2 + b1v.w * eff3;
#pragma unroll
    for (int o = 16; o; o >>= 1) partial += __shfl_xor_sync(0xffffffffu, partial, o);
    return partial + b2[0];
}

// ---------------------------------------------------------------------------
// Kernel 2: main pass — 4 rows per warp, no spills, pipelined reductions
// ---------------------------------------------------------------------------
__global__ __launch_bounds__(256)
void k_main(const float* __restrict__ x,
            const int* __restrict__ batch,
            const float* __restrict__ W1,
            const float* __restrict__ b1,
            const float* __restrict__ W2,
            const float* __restrict__ b2,
            float* __restrict__ out, int n) {
    int warp = (int)((blockIdx.x * blockDim.x + threadIdx.x) >> 5);
    int lane = threadIdx.x & 31;
    int i0 = warp * RPW;
    if (i0 >= n) return;
    int nr = min(RPW, n - i0);

    // lanes 0..nr-1 resolve pos for their row
    int pos_l = 0;
    if (lane < nr) {
        int i = i0 + lane;
        int b = __ldg(&batch[i]);
        if (b != g_lastb) {
            int st;
            if (b >= 0 && b < START_SZ) {
                st = g_start[b];
            } else {
                int lo = 0, hi = i;
                while (lo < hi) {
                    int mid = (lo + hi) >> 1;
                    if (batch[mid] < b) lo = mid + 1; else hi = mid;
                }
                st = lo;
            }
            pos_l = i - st;
        }
    }

    int pos[RPW];
    bool any_slow = false;
#pragma unroll
    for (int r = 0; r < RPW; r++) {
        pos[r] = __shfl_sync(0xffffffffu, pos_l, r);
        if (pos[r] >= PMAX) any_slow = true;
    }

    // independent loads: 4x x-row (streaming) + 4x vtab row (L1/L2) + 4x ctab
    const float4* x4 = reinterpret_cast<const float4*>(x);
    const float4* v4 = reinterpret_cast<const float4*>(g_vtab);
    float4 xv[RPW], vv[RPW];
    float  cval[RPW];
#pragma unroll
    for (int r = 0; r < RPW; r++) {
        int p = pos[r] < PMAX ? pos[r] : 0;
        if (r < nr) {
            xv[r]   = __ldcs(&x4[(size_t)(i0 + r) * (D / 4) + lane]);
            vv[r]   = v4[p * (D / 4) + lane];
            cval[r] = g_ctab[p];
        }
    }

    // per-lane partials
    float partial[RPW];
#pragma unroll
    for (int r = 0; r < RPW; r++) {
        partial[r] = (r < nr)
            ? xv[r].x * vv[r].x + xv[r].y * vv[r].y + xv[r].z * vv[r].z + xv[r].w * vv[r].w
            : 0.f;
    }

    // butterfly reduce — the 4 trees are independent, pipeline across rows
#pragma unroll
    for (int o = 16; o; o >>= 1) {
#pragma unroll
        for (int r = 0; r < RPW; r++)
            partial[r] += __shfl_xor_sync(0xffffffffu, partial[r], o);
    }

    float res_l = 0.f;
#pragma unroll
    for (int r = 0; r < RPW; r++) {
        float v;
        if (any_slow && pos[r] >= PMAX && r < nr) {
            v = row_slow(xv[r], pos[r], W1, b1, W2, b2, lane);
        } else {
            v = partial[r] + ((r < nr) ? cval[r] : 0.f);
        }
        if (lane == r) res_l = v;
    }

    if (lane < nr) out[i0 + lane] = res_l;
}

// ---------------------------------------------------------------------------
extern "C" void kernel_launch(void* const* d_in, const int* in_sizes, int n_in,
                              void* d_out, int out_size) {
    const float* x     = (const float*)d_in[0];
    const int*   batch = (const int*)d_in[1];   // int32 (JAX x64 disabled)
    const float* W1    = (const float*)d_in[2];
    const float* b1    = (const float*)d_in[3];
    const float* W2    = (const float*)d_in[4];
    const float* b2    = (const float*)d_in[5];
    float*       out   = (float*)d_out;
    int n = in_sizes[1];

    k_bounds<<<(n + 255) / 256, 256>>>(batch, n);
    k_table<<<PMAX, D>>>(W1, b1, W2, b2);
    int warps = (n + RPW - 1) / RPW;
    int blocks = (warps * 32 + 255) / 256;
    k_main<<<blocks, 256>>>(x, batch, W1, b1, W2, b2, out, n);
}

// round 13
// speedup vs baseline: 1.8082x; 1.0001x over previous
#include <cuda_runtime.h>

#define D 128
#define PMAX 512
#define START_SZ 16384
#define RPW 4

__device__ float g_vtab[PMAX * D];
__device__ float g_ctab[PMAX];
__device__ int   g_start[START_SZ];
__device__ int   g_lastb;

// ---------------------------------------------------------------------------
// Kernel 0: segment boundaries + last segment id (batch is int32)
// ---------------------------------------------------------------------------
__global__ void k_bounds(const int* __restrict__ batch, int n) {
    int i = blockIdx.x * blockDim.x + threadIdx.x;
    if (i >= n) return;
    int b = batch[i];
    if (i == 0 || batch[i - 1] != b) {
        if (b >= 0 && b < START_SZ) g_start[b] = i;
    }
    if (i == n - 1) g_lastb = b;
}

// ---------------------------------------------------------------------------
// Kernel 1: per-position fused weight table
// ---------------------------------------------------------------------------
__global__ void k_table(const float* __restrict__ W1, const float* __restrict__ b1,
                        const float* __restrict__ W2, const float* __restrict__ b2) {
    __shared__ float eff[D];
    int p = blockIdx.x;
    int t = threadIdx.x;
    if (t < D / 2) {
        double theta = pow(10000.0, -2.0 * t / (double)D);
        double ang = (double)p * theta;
        double c = cos(ang), s = sin(ang);
        float w0 = W2[2 * t], w1 = W2[2 * t + 1];
        eff[2 * t]     = (float)(w0 * c + w1 * s);
        eff[2 * t + 1] = (float)(w1 * c - w0 * s);
    }
    __syncthreads();
    float acc = 0.f;
#pragma unroll 8
    for (int d = 0; d < D; d++)
        acc = fmaf(W1[d * D + t], eff[d], acc);
    g_vtab[p * D + t] = acc;
    if (t == 0) {
        float cb = b2[0];
        for (int d = 0; d < D; d++) cb = fmaf(b1[d], eff[d], cb);
        g_ctab[p] = cb;
    }
}

// ---------------------------------------------------------------------------
// Slow path (pos >= PMAX, never expected on this input)
// ---------------------------------------------------------------------------
__device__ float row_slow(const float4 xv, int pos,
                          const float* __restrict__ W1,
                          const float* __restrict__ b1,
                          const float* __restrict__ W2,
                          const float* __restrict__ b2, int lane) {
    float4 w2v = reinterpret_cast<const float4*>(W2)[lane];
    float eff0, eff1, eff2, eff3;
    {
        int j0 = 2 * lane;
        double th0 = pow(10000.0, -2.0 * j0 / (double)D);
        double a0 = (double)pos * th0;
        double c0 = cos(a0), s0 = sin(a0);
        eff0 = (float)(w2v.x * c0 + w2v.y * s0);
        eff1 = (float)(w2v.y * c0 - w2v.x * s0);
        int j1 = 2 * lane + 1;
        double th1 = pow(10000.0, -2.0 * j1 / (double)D);
        double a1 = (double)pos * th1;
        double c1 = cos(a1), s1 = sin(a1);
        eff2 = (float)(w2v.z * c1 + w2v.w * s1);
        eff3 = (float)(w2v.w * c1 - w2v.z * s1);
    }
    float4 acc = make_float4(0.f, 0.f, 0.f, 0.f);
    const float4* W1r = reinterpret_cast<const float4*>(W1);
    for (int src = 0; src < 32; src++) {
        float e0 = __shfl_sync(0xffffffffu, eff0, src);
        float e1 = __shfl_sync(0xffffffffu, eff1, src);
        float e2 = __shfl_sync(0xffffffffu, eff2, src);
        float e3 = __shfl_sync(0xffffffffu, eff3, src);
        float4 a = W1r[(4 * src + 0) * (D / 4) + lane];
        acc.x = fmaf(a.x, e0, acc.x); acc.y = fmaf(a.y, e0, acc.y);
        acc.z = fmaf(a.z, e0, acc.z); acc.w = fmaf(a.w, e0, acc.w);
        float4 bq = W1r[(4 * src + 1) * (D / 4) + lane];
        acc.x = fmaf(bq.x, e1, acc.x); acc.y = fmaf(bq.y, e1, acc.y);
        acc.z = fmaf(bq.z, e1, acc.z); acc.w = fmaf(bq.w, e1, acc.w);
        float4 cq = W1r[(4 * src + 2) * (D / 4) + lane];
        acc.x = fmaf(cq.x, e2, acc.x); acc.y = fmaf(cq.y, e2, acc.y);
        acc.z = fmaf(cq.z, e2, acc.z); acc.w = fmaf(cq.w, e2, acc.w);
        float4 dq = W1r[(4 * src + 3) * (D / 4) + lane];
        acc.x = fmaf(dq.x, e3, acc.x); acc.y = fmaf(dq.y, e3, acc.y);
        acc.z = fmaf(dq.z, e3, acc.z); acc.w = fmaf(dq.w, e3, acc.w);
    }
    float4 b1v = reinterpret_cast<const float4*>(b1)[lane];
    float partial = xv.x * acc.x + xv.y * acc.y + xv.z * acc.z + xv.w * acc.w
                  + b1v.x * eff0 + b1v.y * eff1 + b1v.z * eff2 + b1v.w * eff3;
#pragma unroll
    for (int o = 16; o; o >>= 1) partial += __shfl_xor_sync(0xffffffffu, partial, o);
    return partial + b2[0];
}

// ---------------------------------------------------------------------------
// Group state (kept fully in registers; two instances = 2-deep pipeline)
// ---------------------------------------------------------------------------
struct Grp {
    float4 xv[RPW];
    float4 vv[RPW];
    int    pos[RPW];
    int    i0, nr;
};

__device__ __forceinline__ void grp_load(Grp& G, int g, int n, int lane, int lastb,
                                         const float4* __restrict__ x4,
                                         const int*    __restrict__ batch) {
    G.i0 = g * RPW;
    G.nr = min(RPW, n - G.i0);

    int pos_l = 0;
    if (lane < G.nr) {
        int i = G.i0 + lane;
        int b = __ldg(&batch[i]);
        if (b != lastb) {
            int st;
            if (b >= 0 && b < START_SZ) {
                st = g_start[b];
            } else {
                int lo = 0, hi = i;
                while (lo < hi) {
                    int mid = (lo + hi) >> 1;
                    if (batch[mid] < b) lo = mid + 1; else hi = mid;
                }
                st = lo;
            }
            pos_l = i - st;
        }
    }
    const float4* v4 = reinterpret_cast<const float4*>(g_vtab);
#pragma unroll
    for (int r = 0; r < RPW; r++) {
        G.pos[r] = __shfl_sync(0xffffffffu, pos_l, r);
        if (r < G.nr) {
            int p = G.pos[r] < PMAX ? G.pos[r] : 0;
            G.xv[r] = __ldcs(&x4[(size_t)(G.i0 + r) * (D / 4) + lane]);
            G.vv[r] = v4[p * (D / 4) + lane];
        }
    }
}

__device__ __forceinline__ void grp_compute(Grp& G, int lane,
                                            const float* __restrict__ W1,
                                            const float* __restrict__ b1,
                                            const float* __restrict__ W2,
                                            const float* __restrict__ b2,
                                            float* __restrict__ out) {
    float partial[RPW];
    bool any_slow = false;
#pragma unroll
    for (int r = 0; r < RPW; r++) {
        partial[r] = (r < G.nr)
            ? G.xv[r].x * G.vv[r].x + G.xv[r].y * G.vv[r].y
            + G.xv[r].z * G.vv[r].z + G.xv[r].w * G.vv[r].w
            : 0.f;
        if (G.pos[r] >= PMAX && r < G.nr) any_slow = true;
    }
#pragma unroll
    for (int o = 16; o; o >>= 1) {
#pragma unroll
        for (int r = 0; r < RPW; r++)
            partial[r] += __shfl_xor_sync(0xffffffffu, partial[r], o);
    }
    float res_l = 0.f;
#pragma unroll
    for (int r = 0; r < RPW; r++) {
        float v;
        if (any_slow && G.pos[r] >= PMAX && r < G.nr) {
            v = row_slow(G.xv[r], G.pos[r], W1, b1, W2, b2, lane);
        } else {
            v = partial[r] + ((r < G.nr) ? g_ctab[G.pos[r] < PMAX ? G.pos[r] : 0] : 0.f);
        }
        if (lane == r) res_l = v;
    }
    if (lane < G.nr) out[G.i0 + lane] = res_l;
}

// ---------------------------------------------------------------------------
// Kernel 2: persistent warps, grid-stride over groups, 2-deep pipeline
// ---------------------------------------------------------------------------
__global__ __launch_bounds__(256)
void k_main(const float* __restrict__ x,
            const int* __restrict__ batch,
            const float* __restrict__ W1,
            const float* __restrict__ b1,
            const float* __restrict__ W2,
            const float* __restrict__ b2,
            float* __restrict__ out, int n) {
    int lane = threadIdx.x & 31;
    int warp = (int)((blockIdx.x * blockDim.x + threadIdx.x) >> 5);
    int nwarps = (int)((gridDim.x * blockDim.x) >> 5);
    int ngroups = (n + RPW - 1) / RPW;
    const float4* x4 = reinterpret_cast<const float4*>(x);
    int lastb = g_lastb;

    int g0 = warp;
    if (g0 >= ngroups) return;

    Grp A, B;
    grp_load(A, g0, n, lane, lastb, x4, batch);
    for (;;) {
        int g1 = g0 + nwarps;
        if (g1 < ngroups) grp_load(B, g1, n, lane, lastb, x4, batch);
        grp_compute(A, lane, W1, b1, W2, b2, out);
        if (g1 >= ngroups) return;

        int g2 = g1 + nwarps;
        if (g2 < ngroups) grp_load(A, g2, n, lane, lastb, x4, batch);
        grp_compute(B, lane, W1, b1, W2, b2, out);
        if (g2 >= ngroups) return;
        g0 = g2;
    }
}

// ---------------------------------------------------------------------------
extern "C" void kernel_launch(void* const* d_in, const int* in_sizes, int n_in,
                              void* d_out, int out_size) {
    const float* x     = (const float*)d_in[0];
    const int*   batch = (const int*)d_in[1];   // int32 (JAX x64 disabled)
    const float* W1    = (const float*)d_in[2];
    const float* b1    = (const float*)d_in[3];
    const float* W2    = (const float*)d_in[4];
    const float* b2    = (const float*)d_in[5];
    float*       out   = (float*)d_out;
    int n = in_sizes[1];

    k_bounds<<<(n + 255) / 256, 256>>>(batch, n);
    k_table<<<PMAX, D>>>(W1, b1, W2, b2);
    k_main<<<2048, 256>>>(x, batch, W1, b1, W2, b2, out, n);
}